// round 12
// baseline (speedup 1.0000x reference)
#include <cuda_runtime.h>
#include <cuda_bf16.h>
#include <math.h>
#include <stdint.h>

#define B 4
#define S 2048
#define E 1024
#define H 16
#define HD 64
#define EPS 1.1920928955078125e-07f

#define BMA 128      // q rows per CTA (attn)
#define BNA 64       // kv cols per tile
#define LDT 72       // attn smem row stride (bf16 elems) = 144B, conflict-free
#define LDP 40       // proj smem row stride (bf16 elems) = 80B, conflict-free
#define SMEM_ATTN 73728

// ---------------- scratch (__device__ globals; no allocs allowed) -----------
__device__ float g_Qn[B*H*S*HD];   // fp32 head-major prep output
__device__ float g_Kn[B*H*S*HD];
__device__ __nv_bfloat16 g_Qh[B*H*S*HD], g_Ql[B*H*S*HD];
__device__ __nv_bfloat16 g_Kh[B*H*S*HD], g_Kl[B*H*S*HD];
__device__ __nv_bfloat16 g_Vth[B*H*S*HD], g_Vtl[B*H*S*HD];  // [bh][d][s] TRANSPOSED
__device__ __nv_bfloat16 g_Ch[B*S*E],   g_Cl[B*S*E];
__device__ __nv_bfloat16 g_Wh[E*E],     g_Wl[E*E];

// ---------------- helpers ---------------------------------------------------
__device__ __forceinline__ void mma16816(float d[4], const uint32_t a[4], const uint32_t b[2]) {
    asm volatile(
        "mma.sync.aligned.m16n8k16.row.col.f32.bf16.bf16.f32 "
        "{%0,%1,%2,%3},{%4,%5,%6,%7},{%8,%9},{%0,%1,%2,%3};"
        : "+f"(d[0]), "+f"(d[1]), "+f"(d[2]), "+f"(d[3])
        : "r"(a[0]), "r"(a[1]), "r"(a[2]), "r"(a[3]), "r"(b[0]), "r"(b[1]));
}
__device__ __forceinline__ uint32_t packb(__nv_bfloat16 x, __nv_bfloat16 y) {
    __nv_bfloat162 t = __halves2bfloat162(x, y);
    return *reinterpret_cast<uint32_t*>(&t);
}
__device__ __forceinline__ uint32_t lds32(const __nv_bfloat16* p) {
    return *reinterpret_cast<const uint32_t*>(p);
}

// ---------------- kernel 1: rmsnorm + rope ----------------------------------
__global__ __launch_bounds__(256) void prep_kernel(
    const float* __restrict__ q, const float* __restrict__ k,
    const float* __restrict__ qw, const float* __restrict__ kw)
{
    int warp = (blockIdx.x * blockDim.x + threadIdx.x) >> 5;
    int lane = threadIdx.x & 31;
    int h  = warp & (H - 1);
    int bs = warp >> 4;            // b*S + s
    int s  = bs & (S - 1);
    int b  = bs >> 11;             // /2048

    int gi = bs * E + h * HD + 2 * lane;
    float2 qv = *reinterpret_cast<const float2*>(q + gi);
    float2 kv = *reinterpret_cast<const float2*>(k + gi);

    float inv_f = exp2f(-(float)lane * 0.41524101186092029f);
    float ang = (float)s * inv_f;
    float cs = cosf(ang), sn = sinf(ang);

    float w1q = qw[2 * lane], w2q = qw[2 * lane + 1];
    float w1k = kw[2 * lane], w2k = kw[2 * lane + 1];

    float ssq = qv.x * qv.x + qv.y * qv.y;
    float ssk = kv.x * kv.x + kv.y * kv.y;
    #pragma unroll
    for (int off = 16; off; off >>= 1) {
        ssq += __shfl_xor_sync(0xffffffff, ssq, off);
        ssk += __shfl_xor_sync(0xffffffff, ssk, off);
    }
    float rq = rsqrtf(ssq * (1.0f / HD) + EPS);
    float rk = rsqrtf(ssk * (1.0f / HD) + EPS);

    float qx1 = qv.x * rq * w1q, qx2 = qv.y * rq * w2q;
    float kx1 = kv.x * rk * w1k, kx2 = kv.y * rk * w2k;

    float2 qo = make_float2(qx1 * cs - qx2 * sn, qx1 * sn + qx2 * cs);
    float2 ko = make_float2(kx1 * cs - kx2 * sn, kx1 * sn + kx2 * cs);

    int oi = ((b * H + h) * S + s) * HD + 2 * lane;
    *reinterpret_cast<float2*>(g_Qn + oi) = qo;
    *reinterpret_cast<float2*>(g_Kn + oi) = ko;
}

// ---------------- kernel 2a: fp32 Q/K -> bf16 hi/lo (scale folded in Q) -----
__global__ __launch_bounds__(256) void convqk_kernel()
{
    int u = blockIdx.x * 256 + threadIdx.x;   // pair id
    int i = u * 2;
    const float sc = 0.125f * 1.4426950408889634f; // HD^-0.5 * log2(e)
    float2 qv = *reinterpret_cast<const float2*>(g_Qn + i);
    float2 kv = *reinterpret_cast<const float2*>(g_Kn + i);
    qv.x *= sc; qv.y *= sc;

    __nv_bfloat16 q0 = __float2bfloat16_rn(qv.x), q1 = __float2bfloat16_rn(qv.y);
    __nv_bfloat16 k0 = __float2bfloat16_rn(kv.x), k1 = __float2bfloat16_rn(kv.y);
    reinterpret_cast<uint32_t*>(g_Qh)[u] = packb(q0, q1);
    reinterpret_cast<uint32_t*>(g_Kh)[u] = packb(k0, k1);
    reinterpret_cast<uint32_t*>(g_Ql)[u] = packb(
        __float2bfloat16_rn(qv.x - __bfloat162float(q0)),
        __float2bfloat16_rn(qv.y - __bfloat162float(q1)));
    reinterpret_cast<uint32_t*>(g_Kl)[u] = packb(
        __float2bfloat16_rn(kv.x - __bfloat162float(k0)),
        __float2bfloat16_rn(kv.y - __bfloat162float(k1)));
}

// ---------------- kernel 2b: v -> TRANSPOSED head-major bf16 hi/lo ----------
// g_Vt[bh][d][s]: block transposes one 64(s) x 64(d) tile via smem.
__global__ __launch_bounds__(256) void convv_kernel(const float* __restrict__ v)
{
    __shared__ float sT[64][65];   // [d][s]
    int st = blockIdx.x, bh = blockIdx.y;
    int b = bh >> 4, h = bh & 15;
    int tid = threadIdx.x;

    #pragma unroll
    for (int i = 0; i < 4; i++) {
        int t = tid + i * 256;
        int sl = t >> 4, d4 = (t & 15) << 2;
        float4 f = *reinterpret_cast<const float4*>(
            v + (size_t)(b * S + st * 64 + sl) * E + h * HD + d4);
        sT[d4 + 0][sl] = f.x;
        sT[d4 + 1][sl] = f.y;
        sT[d4 + 2][sl] = f.z;
        sT[d4 + 3][sl] = f.w;
    }
    __syncthreads();

    int w = tid >> 5, sp = tid & 31;
    #pragma unroll
    for (int i = 0; i < 8; i++) {
        int d = w * 8 + i;
        float x0 = sT[d][2 * sp], x1 = sT[d][2 * sp + 1];
        __nv_bfloat16 h0 = __float2bfloat16_rn(x0), h1 = __float2bfloat16_rn(x1);
        size_t u = ((size_t)(bh * HD + d) * S + st * 64 + 2 * sp) >> 1;
        reinterpret_cast<uint32_t*>(g_Vth)[u] = packb(h0, h1);
        reinterpret_cast<uint32_t*>(g_Vtl)[u] = packb(
            __float2bfloat16_rn(x0 - __bfloat162float(h0)),
            __float2bfloat16_rn(x1 - __bfloat162float(h1)));
    }
}

// ---------------- kernel 2c: W -> bf16 hi/lo --------------------------------
__global__ void wconv_kernel(const float* __restrict__ W) {
    int i = blockIdx.x * 256 + threadIdx.x;
    float x = W[i];
    __nv_bfloat16 hi = __float2bfloat16_rn(x);
    g_Wh[i] = hi;
    g_Wl[i] = __float2bfloat16_rn(x - __bfloat162float(hi));
}

// ---------------- kernel 3: flash attention (no-max softmax, pre-T V) -------
// 256 threads = 8 warps; warp w owns rows [16w,16w+16) of a 128-row q tile.
__global__ __launch_bounds__(256) void attn_kernel()
{
    extern __shared__ __nv_bfloat16 smb[];
    __nv_bfloat16* sQh  = smb;              // [128][LDT]
    __nv_bfloat16* sQl  = smb + 9216;
    __nv_bfloat16* sKh  = smb + 18432;      // [64][LDT]  (row kv, col d)
    __nv_bfloat16* sKl  = smb + 23040;
    __nv_bfloat16* sVth = smb + 27648;      // [64][LDT]  (row d, col kv) from g_Vt
    __nv_bfloat16* sVtl = smb + 32256;

    int bh = blockIdx.y, qt = blockIdx.x;
    int tid = threadIdx.x, w = tid >> 5, t = tid & 31;
    int gid = t >> 2, tig = t & 3;
    int w16 = w * 16;

    size_t base = (size_t)bh * S * HD;
    const __nv_bfloat16* Qhb  = g_Qh + base + (size_t)qt * BMA * HD;
    const __nv_bfloat16* Qlb  = g_Ql + base + (size_t)qt * BMA * HD;
    const __nv_bfloat16* Khb  = g_Kh + base;
    const __nv_bfloat16* Klb  = g_Kl + base;
    const __nv_bfloat16* Vthb = g_Vth + base;   // [d][s]
    const __nv_bfloat16* Vtlb = g_Vtl + base;

    #pragma unroll
    for (int i = 0; i < 4; i++) {
        int lin = i * 256 + tid;
        int r = lin >> 3, c = lin & 7;
        *reinterpret_cast<uint4*>(sQh + r * LDT + c * 8) =
            *reinterpret_cast<const uint4*>(Qhb + r * HD + c * 8);
        *reinterpret_cast<uint4*>(sQl + r * LDT + c * 8) =
            *reinterpret_cast<const uint4*>(Qlb + r * HD + c * 8);
    }

    float accO[8][4];
    #pragma unroll
    for (int j = 0; j < 8; j++)
        #pragma unroll
        for (int c = 0; c < 4; c++) accO[j][c] = 0.f;
    float l0 = 0.f, l1 = 0.f;   // per-thread partial row sums (reduced at end)

    for (int kt = 0; kt < S / BNA; kt++) {
        __syncthreads();
        #pragma unroll
        for (int i = 0; i < 2; i++) {
            int lin = i * 256 + tid;
            int r = lin >> 3, c = lin & 7;   // K: r=kv row; V: r=d row
            size_t gk = (size_t)(kt * BNA + r) * HD + c * 8;
            *reinterpret_cast<uint4*>(sKh + r * LDT + c * 8) =
                *reinterpret_cast<const uint4*>(Khb + gk);
            *reinterpret_cast<uint4*>(sKl + r * LDT + c * 8) =
                *reinterpret_cast<const uint4*>(Klb + gk);
            size_t gv = (size_t)r * S + kt * BNA + c * 8;
            *reinterpret_cast<uint4*>(sVth + r * LDT + c * 8) =
                *reinterpret_cast<const uint4*>(Vthb + gv);
            *reinterpret_cast<uint4*>(sVtl + r * LDT + c * 8) =
                *reinterpret_cast<const uint4*>(Vtlb + gv);
        }
        __syncthreads();

        // ---- S = Q K^T (bf16x3) ----
        float accS[8][4];
        #pragma unroll
        for (int j = 0; j < 8; j++)
            #pragma unroll
            for (int c = 0; c < 4; c++) accS[j][c] = 0.f;

        #pragma unroll
        for (int kk = 0; kk < 4; kk++) {
            int kb = kk * 16 + 2 * tig;
            const __nv_bfloat16* q0h = sQh + (w16 + gid) * LDT + kb;
            const __nv_bfloat16* q0l = sQl + (w16 + gid) * LDT + kb;
            uint32_t ah[4], al[4];
            ah[0] = lds32(q0h);               al[0] = lds32(q0l);
            ah[1] = lds32(q0h + 8 * LDT);     al[1] = lds32(q0l + 8 * LDT);
            ah[2] = lds32(q0h + 8);           al[2] = lds32(q0l + 8);
            ah[3] = lds32(q0h + 8 * LDT + 8); al[3] = lds32(q0l + 8 * LDT + 8);
            #pragma unroll
            for (int j = 0; j < 8; j++) {
                const __nv_bfloat16* kr_h = sKh + (j * 8 + gid) * LDT + kb;
                const __nv_bfloat16* kr_l = sKl + (j * 8 + gid) * LDT + kb;
                uint32_t bhf[2] = { lds32(kr_h), lds32(kr_h + 8) };
                uint32_t blf[2] = { lds32(kr_l), lds32(kr_l + 8) };
                mma16816(accS[j], ah, bhf);
                mma16816(accS[j], ah, blf);
                mma16816(accS[j], al, bhf);
            }
        }

        // ---- softmax numerator: p = exp2(score), fixed max = 0 -------------
        // |score*log2e| <= 8*1.4427 = 11.54 (rmsnorm bounds |q|,|k| = 8), so
        // exp2 cannot overflow; row sums <= 6.1e6 stay comfortably in fp32.
        #pragma unroll
        for (int j = 0; j < 8; j++) {
            accS[j][0] = exp2f(accS[j][0]);
            accS[j][1] = exp2f(accS[j][1]);
            accS[j][2] = exp2f(accS[j][2]);
            accS[j][3] = exp2f(accS[j][3]);
            l0 += accS[j][0] + accS[j][1];
            l1 += accS[j][2] + accS[j][3];
        }

        // ---- O += P V (bf16x3, P register-resident as A fragments) ----
        #pragma unroll
        for (int kk = 0; kk < 4; kk++) {
            const float* p0 = accS[2 * kk];
            const float* p1 = accS[2 * kk + 1];
            __nv_bfloat16 h00 = __float2bfloat16_rn(p0[0]);
            __nv_bfloat16 h01 = __float2bfloat16_rn(p0[1]);
            __nv_bfloat16 h02 = __float2bfloat16_rn(p0[2]);
            __nv_bfloat16 h03 = __float2bfloat16_rn(p0[3]);
            __nv_bfloat16 h10 = __float2bfloat16_rn(p1[0]);
            __nv_bfloat16 h11 = __float2bfloat16_rn(p1[1]);
            __nv_bfloat16 h12 = __float2bfloat16_rn(p1[2]);
            __nv_bfloat16 h13 = __float2bfloat16_rn(p1[3]);
            uint32_t pah[4] = { packb(h00, h01), packb(h02, h03),
                                packb(h10, h11), packb(h12, h13) };
            uint32_t pal[4] = {
                packb(__float2bfloat16_rn(p0[0] - __bfloat162float(h00)),
                      __float2bfloat16_rn(p0[1] - __bfloat162float(h01))),
                packb(__float2bfloat16_rn(p0[2] - __bfloat162float(h02)),
                      __float2bfloat16_rn(p0[3] - __bfloat162float(h03))),
                packb(__float2bfloat16_rn(p1[0] - __bfloat162float(h10)),
                      __float2bfloat16_rn(p1[1] - __bfloat162float(h11))),
                packb(__float2bfloat16_rn(p1[2] - __bfloat162float(h12)),
                      __float2bfloat16_rn(p1[3] - __bfloat162float(h13))) };
            int kvb = kk * 16 + 2 * tig;
            #pragma unroll
            for (int j = 0; j < 8; j++) {
                const __nv_bfloat16* vr_h = sVth + (j * 8 + gid) * LDT + kvb;
                const __nv_bfloat16* vr_l = sVtl + (j * 8 + gid) * LDT + kvb;
                uint32_t vbh[2] = { lds32(vr_h), lds32(vr_h + 8) };
                uint32_t vbl[2] = { lds32(vr_l), lds32(vr_l + 8) };
                mma16816(accO[j], pah, vbh);
                mma16816(accO[j], pah, vbl);
                mma16816(accO[j], pal, vbh);
            }
        }
    }

    // ---- epilogue: one quad reduction of l, normalize, bf16 hi/lo ctx ----
    #pragma unroll
    for (int off = 1; off <= 2; off <<= 1) {
        l0 += __shfl_xor_sync(0xffffffff, l0, off);
        l1 += __shfl_xor_sync(0xffffffff, l1, off);
    }
    int b = bh >> 4, h = bh & 15;
    float i0 = 1.0f / l0, i1 = 1.0f / l1;
    int row0 = b * S + qt * BMA + w16 + gid;
    int row1 = row0 + 8;
    #pragma unroll
    for (int j = 0; j < 8; j++) {
        int col = h * HD + j * 8 + 2 * tig;
        float x0 = accO[j][0] * i0, x1 = accO[j][1] * i0;
        float x2 = accO[j][2] * i1, x3 = accO[j][3] * i1;
        __nv_bfloat16 a0 = __float2bfloat16_rn(x0), a1 = __float2bfloat16_rn(x1);
        __nv_bfloat16 a2 = __float2bfloat16_rn(x2), a3 = __float2bfloat16_rn(x3);
        size_t u0 = ((size_t)row0 * E + col) >> 1;
        size_t u1 = ((size_t)row1 * E + col) >> 1;
        reinterpret_cast<uint32_t*>(g_Ch)[u0] = packb(a0, a1);
        reinterpret_cast<uint32_t*>(g_Ch)[u1] = packb(a2, a3);
        reinterpret_cast<uint32_t*>(g_Cl)[u0] = packb(
            __float2bfloat16_rn(x0 - __bfloat162float(a0)),
            __float2bfloat16_rn(x1 - __bfloat162float(a1)));
        reinterpret_cast<uint32_t*>(g_Cl)[u1] = packb(
            __float2bfloat16_rn(x2 - __bfloat162float(a2)),
            __float2bfloat16_rn(x3 - __bfloat162float(a3)));
    }
}

// ---------------- kernel 4: projection (bf16x3 mma, explicit-LDS frags) -----
__global__ __launch_bounds__(256) void proj_kernel(
    const float* __restrict__ bias, float* __restrict__ out)
{
    __shared__ __nv_bfloat16 sAh[128 * LDP], sAl[128 * LDP];
    __shared__ __nv_bfloat16 sBh[64 * LDP],  sBl[64 * LDP];

    int tid = threadIdx.x, w = tid >> 5, t = tid & 31;
    int gid = t >> 2, tig = t & 3;
    int w16 = w * 16;
    int nb = blockIdx.x * 64, mb = blockIdx.y * 128;

    float acc[8][4];
    #pragma unroll
    for (int j = 0; j < 8; j++)
        #pragma unroll
        for (int c = 0; c < 4; c++) acc[j][c] = 0.f;

    for (int kt = 0; kt < E / 32; kt++) {
        __syncthreads();
        #pragma unroll
        for (int i = 0; i < 2; i++) {
            int lin = i * 256 + tid;
            int r = lin >> 2, c = lin & 3;
            size_t g = (size_t)(mb + r) * E + kt * 32 + c * 8;
            *reinterpret_cast<uint4*>(sAh + r * LDP + c * 8) =
                *reinterpret_cast<const uint4*>(g_Ch + g);
            *reinterpret_cast<uint4*>(sAl + r * LDP + c * 8) =
                *reinterpret_cast<const uint4*>(g_Cl + g);
        }
        {
            int r = tid >> 2, c = tid & 3;
            size_t g = (size_t)(nb + r) * E + kt * 32 + c * 8;
            *reinterpret_cast<uint4*>(sBh + r * LDP + c * 8) =
                *reinterpret_cast<const uint4*>(g_Wh + g);
            *reinterpret_cast<uint4*>(sBl + r * LDP + c * 8) =
                *reinterpret_cast<const uint4*>(g_Wl + g);
        }
        __syncthreads();

        #pragma unroll
        for (int kk = 0; kk < 2; kk++) {
            int kb = kk * 16 + 2 * tig;
            const __nv_bfloat16* a0h = sAh + (w16 + gid) * LDP + kb;
            const __nv_bfloat16* a0l = sAl + (w16 + gid) * LDP + kb;
            uint32_t ah[4], al[4];
            ah[0] = lds32(a0h);               al[0] = lds32(a0l);
            ah[1] = lds32(a0h + 8 * LDP);     al[1] = lds32(a0l + 8 * LDP);
            ah[2] = lds32(a0h + 8);           al[2] = lds32(a0l + 8);
            ah[3] = lds32(a0h + 8 * LDP + 8); al[3] = lds32(a0l + 8 * LDP + 8);
            #pragma unroll
            for (int j = 0; j < 8; j++) {
                const __nv_bfloat16* br_h = sBh + (j * 8 + gid) * LDP + kb;
                const __nv_bfloat16* br_l = sBl + (j * 8 + gid) * LDP + kb;
                uint32_t bhf[2] = { lds32(br_h), lds32(br_h + 8) };
                uint32_t blf[2] = { lds32(br_l), lds32(br_l + 8) };
                mma16816(acc[j], ah, bhf);
                mma16816(acc[j], ah, blf);
                mma16816(acc[j], al, bhf);
            }
        }
    }

    int r0 = mb + w16 + gid, r1 = r0 + 8;
    #pragma unroll
    for (int j = 0; j < 8; j++) {
        int c = nb + j * 8 + 2 * tig;
        float b0 = bias[c], b1 = bias[c + 1];
        float2 o0 = make_float2(acc[j][0] + b0, acc[j][1] + b1);
        float2 o1 = make_float2(acc[j][2] + b0, acc[j][3] + b1);
        *reinterpret_cast<float2*>(out + (size_t)r0 * E + c) = o0;
        *reinterpret_cast<float2*>(out + (size_t)r1 * E + c) = o1;
    }
}

// ---------------------------------------------------------------------------
extern "C" void kernel_launch(void* const* d_in, const int* in_sizes, int n_in,
                              void* d_out, int out_size)
{
    const float* q    = (const float*)d_in[0];
    const float* k    = (const float*)d_in[1];
    const float* v    = (const float*)d_in[2];
    const float* qw   = (const float*)d_in[3];
    const float* kw   = (const float*)d_in[4];
    const float* W    = (const float*)d_in[5];
    const float* bias = (const float*)d_in[6];
    float* out = (float*)d_out;

    cudaFuncSetAttribute(attn_kernel,
                         cudaFuncAttributeMaxDynamicSharedMemorySize, SMEM_ATTN);

    prep_kernel<<<(B * S * H) / 8, 256>>>(q, k, qw, kw);
    convqk_kernel<<<(B * H * S * HD) / 512, 256>>>();
    convv_kernel<<<dim3(S / 64, B * H), 256>>>(v);
    wconv_kernel<<<(E * E) / 256, 256>>>(W);
    attn_kernel<<<dim3(S / BMA, B * H), 256, SMEM_ATTN>>>();
    proj_kernel<<<dim3(E / 64, (B * S) / 128), 256>>>(bias, out);
}

// round 13
// speedup vs baseline: 1.1549x; 1.1549x over previous
#include <cuda_runtime.h>
#include <cuda_bf16.h>
#include <math.h>
#include <stdint.h>

#define B 4
#define S 2048
#define E 1024
#define H 16
#define HD 64
#define EPS 1.1920928955078125e-07f

#define BMA 128      // q rows per CTA (attn)
#define BNA 64       // kv cols per tile
#define LDT 72       // attn smem row stride (bf16 elems) = 144B, conflict-free
#define LDP 40       // proj smem row stride (bf16 elems) = 80B, conflict-free
#define SMEM_ATTN 73728

// ---------------- scratch (__device__ globals; no allocs allowed) -----------
__device__ float g_Qn[B*H*S*HD];   // fp32 head-major prep output
__device__ float g_Kn[B*H*S*HD];
__device__ __nv_bfloat16 g_Qh[B*H*S*HD], g_Ql[B*H*S*HD];
__device__ __nv_bfloat16 g_Kh[B*H*S*HD], g_Kl[B*H*S*HD];
__device__ __nv_bfloat16 g_Vh[B*H*S*HD], g_Vl[B*H*S*HD];
__device__ __nv_bfloat16 g_Ch[B*S*E],   g_Cl[B*S*E];
__device__ __nv_bfloat16 g_Wh[E*E],     g_Wl[E*E];

// ---------------- helpers ---------------------------------------------------
__device__ __forceinline__ void mma16816(float d[4], const uint32_t a[4], const uint32_t b[2]) {
    asm volatile(
        "mma.sync.aligned.m16n8k16.row.col.f32.bf16.bf16.f32 "
        "{%0,%1,%2,%3},{%4,%5,%6,%7},{%8,%9},{%0,%1,%2,%3};"
        : "+f"(d[0]), "+f"(d[1]), "+f"(d[2]), "+f"(d[3])
        : "r"(a[0]), "r"(a[1]), "r"(a[2]), "r"(a[3]), "r"(b[0]), "r"(b[1]));
}
__device__ __forceinline__ uint32_t packb(__nv_bfloat16 x, __nv_bfloat16 y) {
    __nv_bfloat162 t = __halves2bfloat162(x, y);
    return *reinterpret_cast<uint32_t*>(&t);
}
__device__ __forceinline__ uint32_t lds32(const __nv_bfloat16* p) {
    return *reinterpret_cast<const uint32_t*>(p);
}

// ---------------- kernel 1: rmsnorm + rope ----------------------------------
__global__ __launch_bounds__(256) void prep_kernel(
    const float* __restrict__ q, const float* __restrict__ k,
    const float* __restrict__ qw, const float* __restrict__ kw)
{
    int warp = (blockIdx.x * blockDim.x + threadIdx.x) >> 5;
    int lane = threadIdx.x & 31;
    int h  = warp & (H - 1);
    int bs = warp >> 4;            // b*S + s
    int s  = bs & (S - 1);
    int b  = bs >> 11;             // /2048

    int gi = bs * E + h * HD + 2 * lane;
    float2 qv = *reinterpret_cast<const float2*>(q + gi);
    float2 kv = *reinterpret_cast<const float2*>(k + gi);

    float inv_f = exp2f(-(float)lane * 0.41524101186092029f);
    float ang = (float)s * inv_f;
    float cs = cosf(ang), sn = sinf(ang);

    float w1q = qw[2 * lane], w2q = qw[2 * lane + 1];
    float w1k = kw[2 * lane], w2k = kw[2 * lane + 1];

    float ssq = qv.x * qv.x + qv.y * qv.y;
    float ssk = kv.x * kv.x + kv.y * kv.y;
    #pragma unroll
    for (int off = 16; off; off >>= 1) {
        ssq += __shfl_xor_sync(0xffffffff, ssq, off);
        ssk += __shfl_xor_sync(0xffffffff, ssk, off);
    }
    float rq = rsqrtf(ssq * (1.0f / HD) + EPS);
    float rk = rsqrtf(ssk * (1.0f / HD) + EPS);

    float qx1 = qv.x * rq * w1q, qx2 = qv.y * rq * w2q;
    float kx1 = kv.x * rk * w1k, kx2 = kv.y * rk * w2k;

    float2 qo = make_float2(qx1 * cs - qx2 * sn, qx1 * sn + qx2 * cs);
    float2 ko = make_float2(kx1 * cs - kx2 * sn, kx1 * sn + kx2 * cs);

    int oi = ((b * H + h) * S + s) * HD + 2 * lane;
    *reinterpret_cast<float2*>(g_Qn + oi) = qo;
    *reinterpret_cast<float2*>(g_Kn + oi) = ko;
}

// ---------------- kernel 2a: fp32 Q/K -> bf16 hi/lo (scale folded in Q) -----
__global__ __launch_bounds__(256) void convqk_kernel()
{
    int u = blockIdx.x * 256 + threadIdx.x;   // pair id
    int i = u * 2;
    const float sc = 0.125f * 1.4426950408889634f; // HD^-0.5 * log2(e)
    float2 qv = *reinterpret_cast<const float2*>(g_Qn + i);
    float2 kv = *reinterpret_cast<const float2*>(g_Kn + i);
    qv.x *= sc; qv.y *= sc;

    __nv_bfloat16 q0 = __float2bfloat16_rn(qv.x), q1 = __float2bfloat16_rn(qv.y);
    __nv_bfloat16 k0 = __float2bfloat16_rn(kv.x), k1 = __float2bfloat16_rn(kv.y);
    reinterpret_cast<uint32_t*>(g_Qh)[u] = packb(q0, q1);
    reinterpret_cast<uint32_t*>(g_Kh)[u] = packb(k0, k1);
    reinterpret_cast<uint32_t*>(g_Ql)[u] = packb(
        __float2bfloat16_rn(qv.x - __bfloat162float(q0)),
        __float2bfloat16_rn(qv.y - __bfloat162float(q1)));
    reinterpret_cast<uint32_t*>(g_Kl)[u] = packb(
        __float2bfloat16_rn(kv.x - __bfloat162float(k0)),
        __float2bfloat16_rn(kv.y - __bfloat162float(k1)));
}

// ---------------- kernel 2b: v [b,s,e] -> head-major bf16 hi/lo -------------
__global__ __launch_bounds__(256) void convv_kernel(const float* __restrict__ v)
{
    int u = blockIdx.x * 256 + threadIdx.x;   // pair id (head-major)
    int i = u * 2;
    int d  = i & (HD - 1);
    int s  = (i >> 6) & (S - 1);
    int bh = i >> 17;
    int h = bh & (H - 1), b = bh >> 4;
    float2 vv = *reinterpret_cast<const float2*>(
        v + (size_t)(b * S + s) * E + h * HD + d);
    __nv_bfloat16 v0 = __float2bfloat16_rn(vv.x), v1 = __float2bfloat16_rn(vv.y);
    reinterpret_cast<uint32_t*>(g_Vh)[u] = packb(v0, v1);
    reinterpret_cast<uint32_t*>(g_Vl)[u] = packb(
        __float2bfloat16_rn(vv.x - __bfloat162float(v0)),
        __float2bfloat16_rn(vv.y - __bfloat162float(v1)));
}

// ---------------- kernel 2c: W -> bf16 hi/lo --------------------------------
__global__ void wconv_kernel(const float* __restrict__ W) {
    int i = blockIdx.x * 256 + threadIdx.x;
    float x = W[i];
    __nv_bfloat16 hi = __float2bfloat16_rn(x);
    g_Wh[i] = hi;
    g_Wl[i] = __float2bfloat16_rn(x - __bfloat162float(hi));
}

// ---------------- kernel 3: flash attention (R11 body + no-max softmax) -----
// 256 threads = 8 warps; warp w owns rows [16w,16w+16) of a 128-row q tile.
__global__ __launch_bounds__(256) void attn_kernel()
{
    extern __shared__ __nv_bfloat16 smb[];
    __nv_bfloat16* sQh  = smb;              // [128][LDT]
    __nv_bfloat16* sQl  = smb + 9216;
    __nv_bfloat16* sKh  = smb + 18432;      // [64][LDT]  (row kv, col d)
    __nv_bfloat16* sKl  = smb + 23040;
    __nv_bfloat16* sVth = smb + 27648;      // [64][LDT]  V transposed (row d, col kv)
    __nv_bfloat16* sVtl = smb + 32256;

    int bh = blockIdx.y, qt = blockIdx.x;
    int tid = threadIdx.x, w = tid >> 5, t = tid & 31;
    int gid = t >> 2, tig = t & 3;
    int w16 = w * 16;

    size_t base = (size_t)bh * S * HD;
    const __nv_bfloat16* Qhb = g_Qh + base + (size_t)qt * BMA * HD;
    const __nv_bfloat16* Qlb = g_Ql + base + (size_t)qt * BMA * HD;
    const __nv_bfloat16* Khb = g_Kh + base;
    const __nv_bfloat16* Klb = g_Kl + base;
    const __nv_bfloat16* Vhb = g_Vh + base;
    const __nv_bfloat16* Vlb = g_Vl + base;

    #pragma unroll
    for (int i = 0; i < 4; i++) {
        int lin = i * 256 + tid;
        int r = lin >> 3, c = lin & 7;
        *reinterpret_cast<uint4*>(sQh + r * LDT + c * 8) =
            *reinterpret_cast<const uint4*>(Qhb + r * HD + c * 8);
        *reinterpret_cast<uint4*>(sQl + r * LDT + c * 8) =
            *reinterpret_cast<const uint4*>(Qlb + r * HD + c * 8);
    }

    float accO[8][4];
    #pragma unroll
    for (int j = 0; j < 8; j++)
        #pragma unroll
        for (int c = 0; c < 4; c++) accO[j][c] = 0.f;
    float l0 = 0.f, l1 = 0.f;   // per-thread partial row sums (reduced at end)

    for (int kt = 0; kt < S / BNA; kt++) {
        __syncthreads();
        #pragma unroll
        for (int i = 0; i < 2; i++) {
            int lin = i * 256 + tid;
            int r = lin >> 3, c = lin & 7;
            size_t g = (size_t)(kt * BNA + r) * HD + c * 8;
            *reinterpret_cast<uint4*>(sKh + r * LDT + c * 8) =
                *reinterpret_cast<const uint4*>(Khb + g);
            *reinterpret_cast<uint4*>(sKl + r * LDT + c * 8) =
                *reinterpret_cast<const uint4*>(Klb + g);
            uint4 vh = *reinterpret_cast<const uint4*>(Vhb + g);
            uint4 vl = *reinterpret_cast<const uint4*>(Vlb + g);
            const __nv_bfloat16* ph = reinterpret_cast<const __nv_bfloat16*>(&vh);
            const __nv_bfloat16* pl = reinterpret_cast<const __nv_bfloat16*>(&vl);
            #pragma unroll
            for (int jj = 0; jj < 8; jj++) {
                sVth[(c * 8 + jj) * LDT + r] = ph[jj];
                sVtl[(c * 8 + jj) * LDT + r] = pl[jj];
            }
        }
        __syncthreads();

        // ---- S = Q K^T (bf16x3) ----
        float accS[8][4];
        #pragma unroll
        for (int j = 0; j < 8; j++)
            #pragma unroll
            for (int c = 0; c < 4; c++) accS[j][c] = 0.f;

        #pragma unroll
        for (int kk = 0; kk < 4; kk++) {
            int kb = kk * 16 + 2 * tig;
            const __nv_bfloat16* q0h = sQh + (w16 + gid) * LDT + kb;
            const __nv_bfloat16* q0l = sQl + (w16 + gid) * LDT + kb;
            uint32_t ah[4], al[4];
            ah[0] = lds32(q0h);               al[0] = lds32(q0l);
            ah[1] = lds32(q0h + 8 * LDT);     al[1] = lds32(q0l + 8 * LDT);
            ah[2] = lds32(q0h + 8);           al[2] = lds32(q0l + 8);
            ah[3] = lds32(q0h + 8 * LDT + 8); al[3] = lds32(q0l + 8 * LDT + 8);
            #pragma unroll
            for (int j = 0; j < 8; j++) {
                const __nv_bfloat16* kr_h = sKh + (j * 8 + gid) * LDT + kb;
                const __nv_bfloat16* kr_l = sKl + (j * 8 + gid) * LDT + kb;
                uint32_t bhf[2] = { lds32(kr_h), lds32(kr_h + 8) };
                uint32_t blf[2] = { lds32(kr_l), lds32(kr_l + 8) };
                mma16816(accS[j], ah, bhf);
                mma16816(accS[j], ah, blf);
                mma16816(accS[j], al, bhf);
            }
        }

        // ---- softmax numerator: p = exp2(score), fixed max = 0 -------------
        // |score*log2e| <= 8*1.4427 = 11.54 (rmsnorm bounds |q|,|k| = 8), so
        // exp2 cannot overflow; row sums <= 6.1e6 stay comfortably in fp32.
        #pragma unroll
        for (int j = 0; j < 8; j++) {
            accS[j][0] = exp2f(accS[j][0]);
            accS[j][1] = exp2f(accS[j][1]);
            accS[j][2] = exp2f(accS[j][2]);
            accS[j][3] = exp2f(accS[j][3]);
            l0 += accS[j][0] + accS[j][1];
            l1 += accS[j][2] + accS[j][3];
        }

        // ---- O += P V (bf16x3, P register-resident as A fragments) ----
        #pragma unroll
        for (int kk = 0; kk < 4; kk++) {
            const float* p0 = accS[2 * kk];
            const float* p1 = accS[2 * kk + 1];
            __nv_bfloat16 h00 = __float2bfloat16_rn(p0[0]);
            __nv_bfloat16 h01 = __float2bfloat16_rn(p0[1]);
            __nv_bfloat16 h02 = __float2bfloat16_rn(p0[2]);
            __nv_bfloat16 h03 = __float2bfloat16_rn(p0[3]);
            __nv_bfloat16 h10 = __float2bfloat16_rn(p1[0]);
            __nv_bfloat16 h11 = __float2bfloat16_rn(p1[1]);
            __nv_bfloat16 h12 = __float2bfloat16_rn(p1[2]);
            __nv_bfloat16 h13 = __float2bfloat16_rn(p1[3]);
            uint32_t pah[4] = { packb(h00, h01), packb(h02, h03),
                                packb(h10, h11), packb(h12, h13) };
            uint32_t pal[4] = {
                packb(__float2bfloat16_rn(p0[0] - __bfloat162float(h00)),
                      __float2bfloat16_rn(p0[1] - __bfloat162float(h01))),
                packb(__float2bfloat16_rn(p0[2] - __bfloat162float(h02)),
                      __float2bfloat16_rn(p0[3] - __bfloat162float(h03))),
                packb(__float2bfloat16_rn(p1[0] - __bfloat162float(h10)),
                      __float2bfloat16_rn(p1[1] - __bfloat162float(h11))),
                packb(__float2bfloat16_rn(p1[2] - __bfloat162float(h12)),
                      __float2bfloat16_rn(p1[3] - __bfloat162float(h13))) };
            int kvb = kk * 16 + 2 * tig;
            #pragma unroll
            for (int j = 0; j < 8; j++) {
                const __nv_bfloat16* vr_h = sVth + (j * 8 + gid) * LDT + kvb;
                const __nv_bfloat16* vr_l = sVtl + (j * 8 + gid) * LDT + kvb;
                uint32_t vbh[2] = { lds32(vr_h), lds32(vr_h + 8) };
                uint32_t vbl[2] = { lds32(vr_l), lds32(vr_l + 8) };
                mma16816(accO[j], pah, vbh);
                mma16816(accO[j], pah, vbl);
                mma16816(accO[j], pal, vbh);
            }
        }
    }

    // ---- epilogue: one quad reduction of l, normalize, bf16 hi/lo ctx ----
    #pragma unroll
    for (int off = 1; off <= 2; off <<= 1) {
        l0 += __shfl_xor_sync(0xffffffff, l0, off);
        l1 += __shfl_xor_sync(0xffffffff, l1, off);
    }
    int b = bh >> 4, h = bh & 15;
    float i0 = 1.0f / l0, i1 = 1.0f / l1;
    int row0 = b * S + qt * BMA + w16 + gid;
    int row1 = row0 + 8;
    #pragma unroll
    for (int j = 0; j < 8; j++) {
        int col = h * HD + j * 8 + 2 * tig;
        float x0 = accO[j][0] * i0, x1 = accO[j][1] * i0;
        float x2 = accO[j][2] * i1, x3 = accO[j][3] * i1;
        __nv_bfloat16 a0 = __float2bfloat16_rn(x0), a1 = __float2bfloat16_rn(x1);
        __nv_bfloat16 a2 = __float2bfloat16_rn(x2), a3 = __float2bfloat16_rn(x3);
        size_t u0 = ((size_t)row0 * E + col) >> 1;
        size_t u1 = ((size_t)row1 * E + col) >> 1;
        reinterpret_cast<uint32_t*>(g_Ch)[u0] = packb(a0, a1);
        reinterpret_cast<uint32_t*>(g_Ch)[u1] = packb(a2, a3);
        reinterpret_cast<uint32_t*>(g_Cl)[u0] = packb(
            __float2bfloat16_rn(x0 - __bfloat162float(a0)),
            __float2bfloat16_rn(x1 - __bfloat162float(a1)));
        reinterpret_cast<uint32_t*>(g_Cl)[u1] = packb(
            __float2bfloat16_rn(x2 - __bfloat162float(a2)),
            __float2bfloat16_rn(x3 - __bfloat162float(a3)));
    }
}

// ---------------- kernel 4: projection (bf16x3 mma, explicit-LDS frags) -----
__global__ __launch_bounds__(256) void proj_kernel(
    const float* __restrict__ bias, float* __restrict__ out)
{
    __shared__ __nv_bfloat16 sAh[128 * LDP], sAl[128 * LDP];
    __shared__ __nv_bfloat16 sBh[64 * LDP],  sBl[64 * LDP];

    int tid = threadIdx.x, w = tid >> 5, t = tid & 31;
    int gid = t >> 2, tig = t & 3;
    int w16 = w * 16;
    int nb = blockIdx.x * 64, mb = blockIdx.y * 128;

    float acc[8][4];
    #pragma unroll
    for (int j = 0; j < 8; j++)
        #pragma unroll
        for (int c = 0; c < 4; c++) acc[j][c] = 0.f;

    for (int kt = 0; kt < E / 32; kt++) {
        __syncthreads();
        #pragma unroll
        for (int i = 0; i < 2; i++) {
            int lin = i * 256 + tid;
            int r = lin >> 2, c = lin & 3;
            size_t g = (size_t)(mb + r) * E + kt * 32 + c * 8;
            *reinterpret_cast<uint4*>(sAh + r * LDP + c * 8) =
                *reinterpret_cast<const uint4*>(g_Ch + g);
            *reinterpret_cast<uint4*>(sAl + r * LDP + c * 8) =
                *reinterpret_cast<const uint4*>(g_Cl + g);
        }
        {
            int r = tid >> 2, c = tid & 3;
            size_t g = (size_t)(nb + r) * E + kt * 32 + c * 8;
            *reinterpret_cast<uint4*>(sBh + r * LDP + c * 8) =
                *reinterpret_cast<const uint4*>(g_Wh + g);
            *reinterpret_cast<uint4*>(sBl + r * LDP + c * 8) =
                *reinterpret_cast<const uint4*>(g_Wl + g);
        }
        __syncthreads();

        #pragma unroll
        for (int kk = 0; kk < 2; kk++) {
            int kb = kk * 16 + 2 * tig;
            const __nv_bfloat16* a0h = sAh + (w16 + gid) * LDP + kb;
            const __nv_bfloat16* a0l = sAl + (w16 + gid) * LDP + kb;
            uint32_t ah[4], al[4];
            ah[0] = lds32(a0h);               al[0] = lds32(a0l);
            ah[1] = lds32(a0h + 8 * LDP);     al[1] = lds32(a0l + 8 * LDP);
            ah[2] = lds32(a0h + 8);           al[2] = lds32(a0l + 8);
            ah[3] = lds32(a0h + 8 * LDP + 8); al[3] = lds32(a0l + 8 * LDP + 8);
            #pragma unroll
            for (int j = 0; j < 8; j++) {
                const __nv_bfloat16* br_h = sBh + (j * 8 + gid) * LDP + kb;
                const __nv_bfloat16* br_l = sBl + (j * 8 + gid) * LDP + kb;
                uint32_t bhf[2] = { lds32(br_h), lds32(br_h + 8) };
                uint32_t blf[2] = { lds32(br_l), lds32(br_l + 8) };
                mma16816(acc[j], ah, bhf);
                mma16816(acc[j], ah, blf);
                mma16816(acc[j], al, bhf);
            }
        }
    }

    int r0 = mb + w16 + gid, r1 = r0 + 8;
    #pragma unroll
    for (int j = 0; j < 8; j++) {
        int c = nb + j * 8 + 2 * tig;
        float b0 = bias[c], b1 = bias[c + 1];
        float2 o0 = make_float2(acc[j][0] + b0, acc[j][1] + b1);
        float2 o1 = make_float2(acc[j][2] + b0, acc[j][3] + b1);
        *reinterpret_cast<float2*>(out + (size_t)r0 * E + c) = o0;
        *reinterpret_cast<float2*>(out + (size_t)r1 * E + c) = o1;
    }
}

// ---------------------------------------------------------------------------
extern "C" void kernel_launch(void* const* d_in, const int* in_sizes, int n_in,
                              void* d_out, int out_size)
{
    const float* q    = (const float*)d_in[0];
    const float* k    = (const float*)d_in[1];
    const float* v    = (const float*)d_in[2];
    const float* qw   = (const float*)d_in[3];
    const float* kw   = (const float*)d_in[4];
    const float* W    = (const float*)d_in[5];
    const float* bias = (const float*)d_in[6];
    float* out = (float*)d_out;

    cudaFuncSetAttribute(attn_kernel,
                         cudaFuncAttributeMaxDynamicSharedMemorySize, SMEM_ATTN);

    prep_kernel<<<(B * S * H) / 8, 256>>>(q, k, qw, kw);
    convqk_kernel<<<(B * H * S * HD) / 512, 256>>>();
    convv_kernel<<<(B * H * S * HD) / 512, 256>>>(v);
    wconv_kernel<<<(E * E) / 256, 256>>>(W);
    attn_kernel<<<dim3(S / BMA, B * H), 256, SMEM_ATTN>>>();
    proj_kernel<<<dim3(E / 64, (B * S) / 128), 256>>>(bias, out);
}

// round 14
// speedup vs baseline: 1.1857x; 1.0267x over previous
#include <cuda_runtime.h>
#include <cuda_bf16.h>
#include <math.h>
#include <stdint.h>

#define B 4
#define S 2048
#define E 1024
#define H 16
#define HD 64
#define EPS 1.1920928955078125e-07f

#define BMA 128      // q rows per CTA (attn)
#define BNA 64       // kv cols per tile
#define LDT 72       // attn smem row stride (bf16 elems) = 144B, conflict-free
#define LDP 40       // proj smem row stride (bf16 elems) = 80B, conflict-free
#define SMEM_ATTN 73728

// ---------------- scratch (__device__ globals; no allocs allowed) -----------
__device__ __nv_bfloat16 g_Qh[B*H*S*HD], g_Ql[B*H*S*HD];
__device__ __nv_bfloat16 g_Kh[B*H*S*HD], g_Kl[B*H*S*HD];
__device__ __nv_bfloat16 g_Vh[B*H*S*HD], g_Vl[B*H*S*HD];
__device__ __nv_bfloat16 g_Ch[B*S*E],   g_Cl[B*S*E];
__device__ __nv_bfloat16 g_Wh[E*E],     g_Wl[E*E];

// ---------------- helpers ---------------------------------------------------
__device__ __forceinline__ void mma16816(float d[4], const uint32_t a[4], const uint32_t b[2]) {
    asm volatile(
        "mma.sync.aligned.m16n8k16.row.col.f32.bf16.bf16.f32 "
        "{%0,%1,%2,%3},{%4,%5,%6,%7},{%8,%9},{%0,%1,%2,%3};"
        : "+f"(d[0]), "+f"(d[1]), "+f"(d[2]), "+f"(d[3])
        : "r"(a[0]), "r"(a[1]), "r"(a[2]), "r"(a[3]), "r"(b[0]), "r"(b[1]));
}
__device__ __forceinline__ uint32_t packb(__nv_bfloat16 x, __nv_bfloat16 y) {
    __nv_bfloat162 t = __halves2bfloat162(x, y);
    return *reinterpret_cast<uint32_t*>(&t);
}
__device__ __forceinline__ uint32_t lds32(const __nv_bfloat16* p) {
    return *reinterpret_cast<const uint32_t*>(p);
}
__device__ __forceinline__ void split2(float x, float y, uint32_t& hi, uint32_t& lo) {
    __nv_bfloat16 h0 = __float2bfloat16_rn(x), h1 = __float2bfloat16_rn(y);
    hi = packb(h0, h1);
    lo = packb(__float2bfloat16_rn(x - __bfloat162float(h0)),
               __float2bfloat16_rn(y - __bfloat162float(h1)));
}

// ---------------- kernel 1: fused rmsnorm + rope + bf16 hi/lo split ---------
// One warp per (b,s,h) row; lane j owns pair (2j, 2j+1). Math is bit-identical
// to the R13-proven prep + convqk + convv chain (exp2f inv_freq, cosf/sinf,
// scale folded into Q at split time, same rounding sequence).
__global__ __launch_bounds__(256) void prep_kernel(
    const float* __restrict__ q, const float* __restrict__ k,
    const float* __restrict__ v,
    const float* __restrict__ qw, const float* __restrict__ kw)
{
    int warp = (blockIdx.x * blockDim.x + threadIdx.x) >> 5;
    int lane = threadIdx.x & 31;
    int h  = warp & (H - 1);
    int bs = warp >> 4;            // b*S + s
    int s  = bs & (S - 1);
    int b  = bs >> 11;             // /2048

    int gi = bs * E + h * HD + 2 * lane;
    float2 qv = *reinterpret_cast<const float2*>(q + gi);
    float2 kv = *reinterpret_cast<const float2*>(k + gi);
    float2 vv = *reinterpret_cast<const float2*>(v + gi);

    float inv_f = exp2f(-(float)lane * 0.41524101186092029f);
    float ang = (float)s * inv_f;
    float cs = cosf(ang), sn = sinf(ang);

    float w1q = qw[2 * lane], w2q = qw[2 * lane + 1];
    float w1k = kw[2 * lane], w2k = kw[2 * lane + 1];

    float ssq = qv.x * qv.x + qv.y * qv.y;
    float ssk = kv.x * kv.x + kv.y * kv.y;
    #pragma unroll
    for (int off = 16; off; off >>= 1) {
        ssq += __shfl_xor_sync(0xffffffff, ssq, off);
        ssk += __shfl_xor_sync(0xffffffff, ssk, off);
    }
    float rq = rsqrtf(ssq * (1.0f / HD) + EPS);
    float rk = rsqrtf(ssk * (1.0f / HD) + EPS);

    float qx1 = qv.x * rq * w1q, qx2 = qv.y * rq * w2q;
    float kx1 = kv.x * rk * w1k, kx2 = kv.y * rk * w2k;

    // fp32 normed+roped values (same arithmetic as R13 prep output)
    float qox = qx1 * cs - qx2 * sn, qoy = qx1 * sn + qx2 * cs;
    float kox = kx1 * cs - kx2 * sn, koy = kx1 * sn + kx2 * cs;

    // scale fold exactly as convqk did (multiply AFTER rope, before split)
    const float sc = 0.125f * 1.4426950408889634f; // HD^-0.5 * log2(e)
    qox *= sc; qoy *= sc;

    int u = (((b * H + h) * S + s) * HD + 2 * lane) >> 1;
    uint32_t hi, lo;
    split2(qox, qoy, hi, lo);
    reinterpret_cast<uint32_t*>(g_Qh)[u] = hi;
    reinterpret_cast<uint32_t*>(g_Ql)[u] = lo;
    split2(kox, koy, hi, lo);
    reinterpret_cast<uint32_t*>(g_Kh)[u] = hi;
    reinterpret_cast<uint32_t*>(g_Kl)[u] = lo;
    split2(vv.x, vv.y, hi, lo);
    reinterpret_cast<uint32_t*>(g_Vh)[u] = hi;
    reinterpret_cast<uint32_t*>(g_Vl)[u] = lo;
}

// ---------------- kernel 2: W -> bf16 hi/lo ---------------------------------
__global__ void wconv_kernel(const float* __restrict__ W) {
    int i = blockIdx.x * 256 + threadIdx.x;
    float x = W[i];
    __nv_bfloat16 hi = __float2bfloat16_rn(x);
    g_Wh[i] = hi;
    g_Wl[i] = __float2bfloat16_rn(x - __bfloat162float(hi));
}

// ---------------- kernel 3: flash attention (R13-proven body, unchanged) ----
// 256 threads = 8 warps; warp w owns rows [16w,16w+16) of a 128-row q tile.
__global__ __launch_bounds__(256) void attn_kernel()
{
    extern __shared__ __nv_bfloat16 smb[];
    __nv_bfloat16* sQh  = smb;              // [128][LDT]
    __nv_bfloat16* sQl  = smb + 9216;
    __nv_bfloat16* sKh  = smb + 18432;      // [64][LDT]  (row kv, col d)
    __nv_bfloat16* sKl  = smb + 23040;
    __nv_bfloat16* sVth = smb + 27648;      // [64][LDT]  V transposed (row d, col kv)
    __nv_bfloat16* sVtl = smb + 32256;

    int bh = blockIdx.y, qt = blockIdx.x;
    int tid = threadIdx.x, w = tid >> 5, t = tid & 31;
    int gid = t >> 2, tig = t & 3;
    int w16 = w * 16;

    size_t base = (size_t)bh * S * HD;
    const __nv_bfloat16* Qhb = g_Qh + base + (size_t)qt * BMA * HD;
    const __nv_bfloat16* Qlb = g_Ql + base + (size_t)qt * BMA * HD;
    const __nv_bfloat16* Khb = g_Kh + base;
    const __nv_bfloat16* Klb = g_Kl + base;
    const __nv_bfloat16* Vhb = g_Vh + base;
    const __nv_bfloat16* Vlb = g_Vl + base;

    #pragma unroll
    for (int i = 0; i < 4; i++) {
        int lin = i * 256 + tid;
        int r = lin >> 3, c = lin & 7;
        *reinterpret_cast<uint4*>(sQh + r * LDT + c * 8) =
            *reinterpret_cast<const uint4*>(Qhb + r * HD + c * 8);
        *reinterpret_cast<uint4*>(sQl + r * LDT + c * 8) =
            *reinterpret_cast<const uint4*>(Qlb + r * HD + c * 8);
    }

    float accO[8][4];
    #pragma unroll
    for (int j = 0; j < 8; j++)
        #pragma unroll
        for (int c = 0; c < 4; c++) accO[j][c] = 0.f;
    float l0 = 0.f, l1 = 0.f;   // per-thread partial row sums (reduced at end)

    for (int kt = 0; kt < S / BNA; kt++) {
        __syncthreads();
        #pragma unroll
        for (int i = 0; i < 2; i++) {
            int lin = i * 256 + tid;
            int r = lin >> 3, c = lin & 7;
            size_t g = (size_t)(kt * BNA + r) * HD + c * 8;
            *reinterpret_cast<uint4*>(sKh + r * LDT + c * 8) =
                *reinterpret_cast<const uint4*>(Khb + g);
            *reinterpret_cast<uint4*>(sKl + r * LDT + c * 8) =
                *reinterpret_cast<const uint4*>(Klb + g);
            uint4 vh = *reinterpret_cast<const uint4*>(Vhb + g);
            uint4 vl = *reinterpret_cast<const uint4*>(Vlb + g);
            const __nv_bfloat16* ph = reinterpret_cast<const __nv_bfloat16*>(&vh);
            const __nv_bfloat16* pl = reinterpret_cast<const __nv_bfloat16*>(&vl);
            #pragma unroll
            for (int jj = 0; jj < 8; jj++) {
                sVth[(c * 8 + jj) * LDT + r] = ph[jj];
                sVtl[(c * 8 + jj) * LDT + r] = pl[jj];
            }
        }
        __syncthreads();

        // ---- S = Q K^T (bf16x3) ----
        float accS[8][4];
        #pragma unroll
        for (int j = 0; j < 8; j++)
            #pragma unroll
            for (int c = 0; c < 4; c++) accS[j][c] = 0.f;

        #pragma unroll
        for (int kk = 0; kk < 4; kk++) {
            int kb = kk * 16 + 2 * tig;
            const __nv_bfloat16* q0h = sQh + (w16 + gid) * LDT + kb;
            const __nv_bfloat16* q0l = sQl + (w16 + gid) * LDT + kb;
            uint32_t ah[4], al[4];
            ah[0] = lds32(q0h);               al[0] = lds32(q0l);
            ah[1] = lds32(q0h + 8 * LDT);     al[1] = lds32(q0l + 8 * LDT);
            ah[2] = lds32(q0h + 8);           al[2] = lds32(q0l + 8);
            ah[3] = lds32(q0h + 8 * LDT + 8); al[3] = lds32(q0l + 8 * LDT + 8);
            #pragma unroll
            for (int j = 0; j < 8; j++) {
                const __nv_bfloat16* kr_h = sKh + (j * 8 + gid) * LDT + kb;
                const __nv_bfloat16* kr_l = sKl + (j * 8 + gid) * LDT + kb;
                uint32_t bhf[2] = { lds32(kr_h), lds32(kr_h + 8) };
                uint32_t blf[2] = { lds32(kr_l), lds32(kr_l + 8) };
                mma16816(accS[j], ah, bhf);
                mma16816(accS[j], ah, blf);
                mma16816(accS[j], al, bhf);
            }
        }

        // ---- softmax numerator: p = exp2(score), fixed max = 0 -------------
        // |score*log2e| <= 8*1.4427 = 11.54 (rmsnorm bounds |q|,|k| = 8), so
        // exp2 cannot overflow; row sums <= 6.1e6 stay comfortably in fp32.
        #pragma unroll
        for (int j = 0; j < 8; j++) {
            accS[j][0] = exp2f(accS[j][0]);
            accS[j][1] = exp2f(accS[j][1]);
            accS[j][2] = exp2f(accS[j][2]);
            accS[j][3] = exp2f(accS[j][3]);
            l0 += accS[j][0] + accS[j][1];
            l1 += accS[j][2] + accS[j][3];
        }

        // ---- O += P V (bf16x3, P register-resident as A fragments) ----
        #pragma unroll
        for (int kk = 0; kk < 4; kk++) {
            const float* p0 = accS[2 * kk];
            const float* p1 = accS[2 * kk + 1];
            __nv_bfloat16 h00 = __float2bfloat16_rn(p0[0]);
            __nv_bfloat16 h01 = __float2bfloat16_rn(p0[1]);
            __nv_bfloat16 h02 = __float2bfloat16_rn(p0[2]);
            __nv_bfloat16 h03 = __float2bfloat16_rn(p0[3]);
            __nv_bfloat16 h10 = __float2bfloat16_rn(p1[0]);
            __nv_bfloat16 h11 = __float2bfloat16_rn(p1[1]);
            __nv_bfloat16 h12 = __float2bfloat16_rn(p1[2]);
            __nv_bfloat16 h13 = __float2bfloat16_rn(p1[3]);
            uint32_t pah[4] = { packb(h00, h01), packb(h02, h03),
                                packb(h10, h11), packb(h12, h13) };
            uint32_t pal[4] = {
                packb(__float2bfloat16_rn(p0[0] - __bfloat162float(h00)),
                      __float2bfloat16_rn(p0[1] - __bfloat162float(h01))),
                packb(__float2bfloat16_rn(p0[2] - __bfloat162float(h02)),
                      __float2bfloat16_rn(p0[3] - __bfloat162float(h03))),
                packb(__float2bfloat16_rn(p1[0] - __bfloat162float(h10)),
                      __float2bfloat16_rn(p1[1] - __bfloat162float(h11))),
                packb(__float2bfloat16_rn(p1[2] - __bfloat162float(h12)),
                      __float2bfloat16_rn(p1[3] - __bfloat162float(h13))) };
            int kvb = kk * 16 + 2 * tig;
            #pragma unroll
            for (int j = 0; j < 8; j++) {
                const __nv_bfloat16* vr_h = sVth + (j * 8 + gid) * LDT + kvb;
                const __nv_bfloat16* vr_l = sVtl + (j * 8 + gid) * LDT + kvb;
                uint32_t vbh[2] = { lds32(vr_h), lds32(vr_h + 8) };
                uint32_t vbl[2] = { lds32(vr_l), lds32(vr_l + 8) };
                mma16816(accO[j], pah, vbh);
                mma16816(accO[j], pah, vbl);
                mma16816(accO[j], pal, vbh);
            }
        }
    }

    // ---- epilogue: one quad reduction of l, normalize, bf16 hi/lo ctx ----
    #pragma unroll
    for (int off = 1; off <= 2; off <<= 1) {
        l0 += __shfl_xor_sync(0xffffffff, l0, off);
        l1 += __shfl_xor_sync(0xffffffff, l1, off);
    }
    int b = bh >> 4, h = bh & 15;
    float i0 = 1.0f / l0, i1 = 1.0f / l1;
    int row0 = b * S + qt * BMA + w16 + gid;
    int row1 = row0 + 8;
    #pragma unroll
    for (int j = 0; j < 8; j++) {
        int col = h * HD + j * 8 + 2 * tig;
        float x0 = accO[j][0] * i0, x1 = accO[j][1] * i0;
        float x2 = accO[j][2] * i1, x3 = accO[j][3] * i1;
        __nv_bfloat16 a0 = __float2bfloat16_rn(x0), a1 = __float2bfloat16_rn(x1);
        __nv_bfloat16 a2 = __float2bfloat16_rn(x2), a3 = __float2bfloat16_rn(x3);
        size_t u0 = ((size_t)row0 * E + col) >> 1;
        size_t u1 = ((size_t)row1 * E + col) >> 1;
        reinterpret_cast<uint32_t*>(g_Ch)[u0] = packb(a0, a1);
        reinterpret_cast<uint32_t*>(g_Ch)[u1] = packb(a2, a3);
        reinterpret_cast<uint32_t*>(g_Cl)[u0] = packb(
            __float2bfloat16_rn(x0 - __bfloat162float(a0)),
            __float2bfloat16_rn(x1 - __bfloat162float(a1)));
        reinterpret_cast<uint32_t*>(g_Cl)[u1] = packb(
            __float2bfloat16_rn(x2 - __bfloat162float(a2)),
            __float2bfloat16_rn(x3 - __bfloat162float(a3)));
    }
}

// ---------------- kernel 4: projection (bf16x3 mma, explicit-LDS frags) -----
__global__ __launch_bounds__(256) void proj_kernel(
    const float* __restrict__ bias, float* __restrict__ out)
{
    __shared__ __nv_bfloat16 sAh[128 * LDP], sAl[128 * LDP];
    __shared__ __nv_bfloat16 sBh[64 * LDP],  sBl[64 * LDP];

    int tid = threadIdx.x, w = tid >> 5, t = tid & 31;
    int gid = t >> 2, tig = t & 3;
    int w16 = w * 16;
    int nb = blockIdx.x * 64, mb = blockIdx.y * 128;

    float acc[8][4];
    #pragma unroll
    for (int j = 0; j < 8; j++)
        #pragma unroll
        for (int c = 0; c < 4; c++) acc[j][c] = 0.f;

    for (int kt = 0; kt < E / 32; kt++) {
        __syncthreads();
        #pragma unroll
        for (int i = 0; i < 2; i++) {
            int lin = i * 256 + tid;
            int r = lin >> 2, c = lin & 3;
            size_t g = (size_t)(mb + r) * E + kt * 32 + c * 8;
            *reinterpret_cast<uint4*>(sAh + r * LDP + c * 8) =
                *reinterpret_cast<const uint4*>(g_Ch + g);
            *reinterpret_cast<uint4*>(sAl + r * LDP + c * 8) =
                *reinterpret_cast<const uint4*>(g_Cl + g);
        }
        {
            int r = tid >> 2, c = tid & 3;
            size_t g = (size_t)(nb + r) * E + kt * 32 + c * 8;
            *reinterpret_cast<uint4*>(sBh + r * LDP + c * 8) =
                *reinterpret_cast<const uint4*>(g_Wh + g);
            *reinterpret_cast<uint4*>(sBl + r * LDP + c * 8) =
                *reinterpret_cast<const uint4*>(g_Wl + g);
        }
        __syncthreads();

        #pragma unroll
        for (int kk = 0; kk < 2; kk++) {
            int kb = kk * 16 + 2 * tig;
            const __nv_bfloat16* a0h = sAh + (w16 + gid) * LDP + kb;
            const __nv_bfloat16* a0l = sAl + (w16 + gid) * LDP + kb;
            uint32_t ah[4], al[4];
            ah[0] = lds32(a0h);               al[0] = lds32(a0l);
            ah[1] = lds32(a0h + 8 * LDP);     al[1] = lds32(a0l + 8 * LDP);
            ah[2] = lds32(a0h + 8);           al[2] = lds32(a0l + 8);
            ah[3] = lds32(a0h + 8 * LDP + 8); al[3] = lds32(a0l + 8 * LDP + 8);
            #pragma unroll
            for (int j = 0; j < 8; j++) {
                const __nv_bfloat16* br_h = sBh + (j * 8 + gid) * LDP + kb;
                const __nv_bfloat16* br_l = sBl + (j * 8 + gid) * LDP + kb;
                uint32_t bhf[2] = { lds32(br_h), lds32(br_h + 8) };
                uint32_t blf[2] = { lds32(br_l), lds32(br_l + 8) };
                mma16816(acc[j], ah, bhf);
                mma16816(acc[j], ah, blf);
                mma16816(acc[j], al, bhf);
            }
        }
    }

    int r0 = mb + w16 + gid, r1 = r0 + 8;
    #pragma unroll
    for (int j = 0; j < 8; j++) {
        int c = nb + j * 8 + 2 * tig;
        float b0 = bias[c], b1 = bias[c + 1];
        float2 o0 = make_float2(acc[j][0] + b0, acc[j][1] + b1);
        float2 o1 = make_float2(acc[j][2] + b0, acc[j][3] + b1);
        *reinterpret_cast<float2*>(out + (size_t)r0 * E + c) = o0;
        *reinterpret_cast<float2*>(out + (size_t)r1 * E + c) = o1;
    }
}

// ---------------------------------------------------------------------------
extern "C" void kernel_launch(void* const* d_in, const int* in_sizes, int n_in,
                              void* d_out, int out_size)
{
    const float* q    = (const float*)d_in[0];
    const float* k    = (const float*)d_in[1];
    const float* v    = (const float*)d_in[2];
    const float* qw   = (const float*)d_in[3];
    const float* kw   = (const float*)d_in[4];
    const float* W    = (const float*)d_in[5];
    const float* bias = (const float*)d_in[6];
    float* out = (float*)d_out;

    cudaFuncSetAttribute(attn_kernel,
                         cudaFuncAttributeMaxDynamicSharedMemorySize, SMEM_ATTN);

    prep_kernel<<<(B * S * H) / 8, 256>>>(q, k, v, qw, kw);
    wconv_kernel<<<(E * E) / 256, 256>>>(W);
    attn_kernel<<<dim3(S / BMA, B * H), 256, SMEM_ATTN>>>();
    proj_kernel<<<dim3(E / 64, (B * S) / 128), 256>>>(bias, out);
}

// round 15
// speedup vs baseline: 1.2610x; 1.0635x over previous
#include <cuda_runtime.h>
#include <cuda_bf16.h>
#include <math.h>
#include <stdint.h>

#define B 4
#define S 2048
#define E 1024
#define H 16
#define HD 64
#define EPS 1.1920928955078125e-07f

#define BMA 128      // q rows per CTA (attn)
#define BNA 64       // kv cols per tile
#define LDT 72       // attn smem row stride (bf16 elems) = 144B, conflict-free
#define LDP 40       // proj smem row stride (bf16 elems) = 80B, conflict-free
#define SMEM_ATTN 73728
#define SMEM_PROJ 51200   // (256*LDP*2 + 64*LDP*2) elems * 2B

// ---------------- scratch (__device__ globals; no allocs allowed) -----------
__device__ __nv_bfloat16 g_Qh[B*H*S*HD], g_Ql[B*H*S*HD];
__device__ __nv_bfloat16 g_Kh[B*H*S*HD], g_Kl[B*H*S*HD];
__device__ __nv_bfloat16 g_Vh[B*H*S*HD], g_Vl[B*H*S*HD];
__device__ __nv_bfloat16 g_Ch[B*S*E],   g_Cl[B*S*E];
__device__ __nv_bfloat16 g_Wh[E*E],     g_Wl[E*E];

// ---------------- helpers ---------------------------------------------------
__device__ __forceinline__ void mma16816(float d[4], const uint32_t a[4], const uint32_t b[2]) {
    asm volatile(
        "mma.sync.aligned.m16n8k16.row.col.f32.bf16.bf16.f32 "
        "{%0,%1,%2,%3},{%4,%5,%6,%7},{%8,%9},{%0,%1,%2,%3};"
        : "+f"(d[0]), "+f"(d[1]), "+f"(d[2]), "+f"(d[3])
        : "r"(a[0]), "r"(a[1]), "r"(a[2]), "r"(a[3]), "r"(b[0]), "r"(b[1]));
}
__device__ __forceinline__ uint32_t packb(__nv_bfloat16 x, __nv_bfloat16 y) {
    __nv_bfloat162 t = __halves2bfloat162(x, y);
    return *reinterpret_cast<uint32_t*>(&t);
}
__device__ __forceinline__ uint32_t lds32(const __nv_bfloat16* p) {
    return *reinterpret_cast<const uint32_t*>(p);
}
// pack two floats to bf16x2 (lo=x, hi=y) with RN — same bits as packb of
// __float2bfloat16_rn pair, one instruction.
__device__ __forceinline__ uint32_t cvtpack(float x, float y) {
    uint32_t r;
    asm("cvt.rn.bf16x2.f32 %0, %1, %2;" : "=r"(r) : "f"(y), "f"(x));
    return r;
}
__device__ __forceinline__ void split2(float x, float y, uint32_t& hi, uint32_t& lo) {
    __nv_bfloat16 h0 = __float2bfloat16_rn(x), h1 = __float2bfloat16_rn(y);
    hi = packb(h0, h1);
    lo = packb(__float2bfloat16_rn(x - __bfloat162float(h0)),
               __float2bfloat16_rn(y - __bfloat162float(h1)));
}

// ---------------- kernel 1: fused rmsnorm + rope + bf16 hi/lo split ---------
__global__ __launch_bounds__(256) void prep_kernel(
    const float* __restrict__ q, const float* __restrict__ k,
    const float* __restrict__ v,
    const float* __restrict__ qw, const float* __restrict__ kw)
{
    int warp = (blockIdx.x * blockDim.x + threadIdx.x) >> 5;
    int lane = threadIdx.x & 31;
    int h  = warp & (H - 1);
    int bs = warp >> 4;            // b*S + s
    int s  = bs & (S - 1);
    int b  = bs >> 11;             // /2048

    int gi = bs * E + h * HD + 2 * lane;
    float2 qv = *reinterpret_cast<const float2*>(q + gi);
    float2 kv = *reinterpret_cast<const float2*>(k + gi);
    float2 vv = *reinterpret_cast<const float2*>(v + gi);

    float inv_f = exp2f(-(float)lane * 0.41524101186092029f);
    float ang = (float)s * inv_f;
    float cs = cosf(ang), sn = sinf(ang);

    float w1q = qw[2 * lane], w2q = qw[2 * lane + 1];
    float w1k = kw[2 * lane], w2k = kw[2 * lane + 1];

    float ssq = qv.x * qv.x + qv.y * qv.y;
    float ssk = kv.x * kv.x + kv.y * kv.y;
    #pragma unroll
    for (int off = 16; off; off >>= 1) {
        ssq += __shfl_xor_sync(0xffffffff, ssq, off);
        ssk += __shfl_xor_sync(0xffffffff, ssk, off);
    }
    float rq = rsqrtf(ssq * (1.0f / HD) + EPS);
    float rk = rsqrtf(ssk * (1.0f / HD) + EPS);

    float qx1 = qv.x * rq * w1q, qx2 = qv.y * rq * w2q;
    float kx1 = kv.x * rk * w1k, kx2 = kv.y * rk * w2k;

    float qox = qx1 * cs - qx2 * sn, qoy = qx1 * sn + qx2 * cs;
    float kox = kx1 * cs - kx2 * sn, koy = kx1 * sn + kx2 * cs;

    const float sc = 0.125f * 1.4426950408889634f; // HD^-0.5 * log2(e)
    qox *= sc; qoy *= sc;

    int u = (((b * H + h) * S + s) * HD + 2 * lane) >> 1;
    uint32_t hi, lo;
    split2(qox, qoy, hi, lo);
    reinterpret_cast<uint32_t*>(g_Qh)[u] = hi;
    reinterpret_cast<uint32_t*>(g_Ql)[u] = lo;
    split2(kox, koy, hi, lo);
    reinterpret_cast<uint32_t*>(g_Kh)[u] = hi;
    reinterpret_cast<uint32_t*>(g_Kl)[u] = lo;
    split2(vv.x, vv.y, hi, lo);
    reinterpret_cast<uint32_t*>(g_Vh)[u] = hi;
    reinterpret_cast<uint32_t*>(g_Vl)[u] = lo;
}

// ---------------- kernel 2: W -> bf16 hi/lo ---------------------------------
__global__ void wconv_kernel(const float* __restrict__ W) {
    int i = blockIdx.x * 256 + threadIdx.x;
    float x = W[i];
    __nv_bfloat16 hi = __float2bfloat16_rn(x);
    g_Wh[i] = hi;
    g_Wl[i] = __float2bfloat16_rn(x - __bfloat162float(hi));
}

// ---------------- kernel 3: flash attention (R13 body + Qhi reg cache) ------
// 256 threads = 8 warps; warp w owns rows [16w,16w+16) of a 128-row q tile.
__global__ __launch_bounds__(256, 2) void attn_kernel()
{
    extern __shared__ __nv_bfloat16 smb[];
    __nv_bfloat16* sQh  = smb;              // [128][LDT]
    __nv_bfloat16* sQl  = smb + 9216;
    __nv_bfloat16* sKh  = smb + 18432;      // [64][LDT]  (row kv, col d)
    __nv_bfloat16* sKl  = smb + 23040;
    __nv_bfloat16* sVth = smb + 27648;      // [64][LDT]  V transposed (row d, col kv)
    __nv_bfloat16* sVtl = smb + 32256;

    int bh = blockIdx.y, qt = blockIdx.x;
    int tid = threadIdx.x, w = tid >> 5, t = tid & 31;
    int gid = t >> 2, tig = t & 3;
    int w16 = w * 16;

    size_t base = (size_t)bh * S * HD;
    const __nv_bfloat16* Qhb = g_Qh + base + (size_t)qt * BMA * HD;
    const __nv_bfloat16* Qlb = g_Ql + base + (size_t)qt * BMA * HD;
    const __nv_bfloat16* Khb = g_Kh + base;
    const __nv_bfloat16* Klb = g_Kl + base;
    const __nv_bfloat16* Vhb = g_Vh + base;
    const __nv_bfloat16* Vlb = g_Vl + base;

    #pragma unroll
    for (int i = 0; i < 4; i++) {
        int lin = i * 256 + tid;
        int r = lin >> 3, c = lin & 7;
        *reinterpret_cast<uint4*>(sQh + r * LDT + c * 8) =
            *reinterpret_cast<const uint4*>(Qhb + r * HD + c * 8);
        *reinterpret_cast<uint4*>(sQl + r * LDT + c * 8) =
            *reinterpret_cast<const uint4*>(Qlb + r * HD + c * 8);
    }
    __syncthreads();

    // Q-hi fragments cached in registers for the whole kv loop (Q constant).
    uint32_t qfh[4][4];
    #pragma unroll
    for (int kk = 0; kk < 4; kk++) {
        int kb = kk * 16 + 2 * tig;
        const __nv_bfloat16* q0h = sQh + (w16 + gid) * LDT + kb;
        qfh[kk][0] = lds32(q0h);
        qfh[kk][1] = lds32(q0h + 8 * LDT);
        qfh[kk][2] = lds32(q0h + 8);
        qfh[kk][3] = lds32(q0h + 8 * LDT + 8);
    }

    float accO[8][4];
    #pragma unroll
    for (int j = 0; j < 8; j++)
        #pragma unroll
        for (int c = 0; c < 4; c++) accO[j][c] = 0.f;
    float l0 = 0.f, l1 = 0.f;

    for (int kt = 0; kt < S / BNA; kt++) {
        __syncthreads();
        #pragma unroll
        for (int i = 0; i < 2; i++) {
            int lin = i * 256 + tid;
            int r = lin >> 3, c = lin & 7;
            size_t g = (size_t)(kt * BNA + r) * HD + c * 8;
            *reinterpret_cast<uint4*>(sKh + r * LDT + c * 8) =
                *reinterpret_cast<const uint4*>(Khb + g);
            *reinterpret_cast<uint4*>(sKl + r * LDT + c * 8) =
                *reinterpret_cast<const uint4*>(Klb + g);
            uint4 vh = *reinterpret_cast<const uint4*>(Vhb + g);
            uint4 vl = *reinterpret_cast<const uint4*>(Vlb + g);
            const __nv_bfloat16* ph = reinterpret_cast<const __nv_bfloat16*>(&vh);
            const __nv_bfloat16* pl = reinterpret_cast<const __nv_bfloat16*>(&vl);
            #pragma unroll
            for (int jj = 0; jj < 8; jj++) {
                sVth[(c * 8 + jj) * LDT + r] = ph[jj];
                sVtl[(c * 8 + jj) * LDT + r] = pl[jj];
            }
        }
        __syncthreads();

        // ---- S = Q K^T (bf16x3) ----
        float accS[8][4];
        #pragma unroll
        for (int j = 0; j < 8; j++)
            #pragma unroll
            for (int c = 0; c < 4; c++) accS[j][c] = 0.f;

        #pragma unroll
        for (int kk = 0; kk < 4; kk++) {
            int kb = kk * 16 + 2 * tig;
            const __nv_bfloat16* q0l = sQl + (w16 + gid) * LDT + kb;
            uint32_t al[4];
            al[0] = lds32(q0l);
            al[1] = lds32(q0l + 8 * LDT);
            al[2] = lds32(q0l + 8);
            al[3] = lds32(q0l + 8 * LDT + 8);
            #pragma unroll
            for (int j = 0; j < 8; j++) {
                const __nv_bfloat16* kr_h = sKh + (j * 8 + gid) * LDT + kb;
                const __nv_bfloat16* kr_l = sKl + (j * 8 + gid) * LDT + kb;
                uint32_t bhf[2] = { lds32(kr_h), lds32(kr_h + 8) };
                uint32_t blf[2] = { lds32(kr_l), lds32(kr_l + 8) };
                mma16816(accS[j], qfh[kk], bhf);
                mma16816(accS[j], qfh[kk], blf);
                mma16816(accS[j], al, bhf);
            }
        }

        // ---- softmax numerator: p = exp2(score), fixed max = 0 -------------
        // |score*log2e| <= 11.54 (rmsnorm bounds |q|,|k| = 8): no overflow.
        #pragma unroll
        for (int j = 0; j < 8; j++) {
            accS[j][0] = exp2f(accS[j][0]);
            accS[j][1] = exp2f(accS[j][1]);
            accS[j][2] = exp2f(accS[j][2]);
            accS[j][3] = exp2f(accS[j][3]);
            l0 += accS[j][0] + accS[j][1];
            l1 += accS[j][2] + accS[j][3];
        }

        // ---- O += P V (bf16x3, P register-resident as A fragments) ----
        #pragma unroll
        for (int kk = 0; kk < 4; kk++) {
            const float* p0 = accS[2 * kk];
            const float* p1 = accS[2 * kk + 1];
            uint32_t pah[4], pal[4];
            #pragma unroll
            for (int hseg = 0; hseg < 4; hseg++) {
                const float* ps = (hseg < 2) ? p0 : p1;
                float x = ps[(hseg & 1) * 2], y = ps[(hseg & 1) * 2 + 1];
                uint32_t hw = cvtpack(x, y);
                pah[hseg] = hw;
                float xh = __uint_as_float(hw << 16);
                float yh = __uint_as_float(hw & 0xffff0000u);
                pal[hseg] = cvtpack(x - xh, y - yh);
            }
            int kvb = kk * 16 + 2 * tig;
            #pragma unroll
            for (int j = 0; j < 8; j++) {
                const __nv_bfloat16* vr_h = sVth + (j * 8 + gid) * LDT + kvb;
                const __nv_bfloat16* vr_l = sVtl + (j * 8 + gid) * LDT + kvb;
                uint32_t vbh[2] = { lds32(vr_h), lds32(vr_h + 8) };
                uint32_t vbl[2] = { lds32(vr_l), lds32(vr_l + 8) };
                mma16816(accO[j], pah, vbh);
                mma16816(accO[j], pah, vbl);
                mma16816(accO[j], pal, vbh);
            }
        }
    }

    // ---- epilogue: one quad reduction of l, normalize, bf16 hi/lo ctx ----
    #pragma unroll
    for (int off = 1; off <= 2; off <<= 1) {
        l0 += __shfl_xor_sync(0xffffffff, l0, off);
        l1 += __shfl_xor_sync(0xffffffff, l1, off);
    }
    int b = bh >> 4, h = bh & 15;
    float i0 = 1.0f / l0, i1 = 1.0f / l1;
    int row0 = b * S + qt * BMA + w16 + gid;
    int row1 = row0 + 8;
    #pragma unroll
    for (int j = 0; j < 8; j++) {
        int col = h * HD + j * 8 + 2 * tig;
        float x0 = accO[j][0] * i0, x1 = accO[j][1] * i0;
        float x2 = accO[j][2] * i1, x3 = accO[j][3] * i1;
        __nv_bfloat16 a0 = __float2bfloat16_rn(x0), a1 = __float2bfloat16_rn(x1);
        __nv_bfloat16 a2 = __float2bfloat16_rn(x2), a3 = __float2bfloat16_rn(x3);
        size_t u0 = ((size_t)row0 * E + col) >> 1;
        size_t u1 = ((size_t)row1 * E + col) >> 1;
        reinterpret_cast<uint32_t*>(g_Ch)[u0] = packb(a0, a1);
        reinterpret_cast<uint32_t*>(g_Ch)[u1] = packb(a2, a3);
        reinterpret_cast<uint32_t*>(g_Cl)[u0] = packb(
            __float2bfloat16_rn(x0 - __bfloat162float(a0)),
            __float2bfloat16_rn(x1 - __bfloat162float(a1)));
        reinterpret_cast<uint32_t*>(g_Cl)[u1] = packb(
            __float2bfloat16_rn(x2 - __bfloat162float(a2)),
            __float2bfloat16_rn(x3 - __bfloat162float(a3)));
    }
}

// ---------------- kernel 4: projection (bf16x3 mma, M=256: 2 blocks/warp) ---
// out[m][n] = sum_k ctx[m][k] * W[n][k] + bias[n]; tile 256x64, K-step 32.
// B fragments shared across both row-blocks: 1.0 LDS/MMA (was 1.67).
__global__ __launch_bounds__(256) void proj_kernel(
    const float* __restrict__ bias, float* __restrict__ out)
{
    extern __shared__ __nv_bfloat16 smp[];
    __nv_bfloat16* sAh = smp;                   // [256][LDP]
    __nv_bfloat16* sAl = smp + 256 * LDP;
    __nv_bfloat16* sBh = smp + 512 * LDP;       // [64][LDP]
    __nv_bfloat16* sBl = smp + 512 * LDP + 64 * LDP;

    int tid = threadIdx.x, w = tid >> 5, t = tid & 31;
    int gid = t >> 2, tig = t & 3;
    int w16 = w * 16;
    int nb = blockIdx.x * 64, mb = blockIdx.y * 256;

    float acc0[8][4], acc1[8][4];
    #pragma unroll
    for (int j = 0; j < 8; j++)
        #pragma unroll
        for (int c = 0; c < 4; c++) { acc0[j][c] = 0.f; acc1[j][c] = 0.f; }

    for (int kt = 0; kt < E / 32; kt++) {
        __syncthreads();
        #pragma unroll
        for (int i = 0; i < 4; i++) {
            int lin = i * 256 + tid;
            int r = lin >> 2, c = lin & 3;
            size_t g = (size_t)(mb + r) * E + kt * 32 + c * 8;
            *reinterpret_cast<uint4*>(sAh + r * LDP + c * 8) =
                *reinterpret_cast<const uint4*>(g_Ch + g);
            *reinterpret_cast<uint4*>(sAl + r * LDP + c * 8) =
                *reinterpret_cast<const uint4*>(g_Cl + g);
        }
        {
            int r = tid >> 2, c = tid & 3;
            size_t g = (size_t)(nb + r) * E + kt * 32 + c * 8;
            *reinterpret_cast<uint4*>(sBh + r * LDP + c * 8) =
                *reinterpret_cast<const uint4*>(g_Wh + g);
            *reinterpret_cast<uint4*>(sBl + r * LDP + c * 8) =
                *reinterpret_cast<const uint4*>(g_Wl + g);
        }
        __syncthreads();

        #pragma unroll
        for (int kk = 0; kk < 2; kk++) {
            int kb = kk * 16 + 2 * tig;
            const __nv_bfloat16* a0h = sAh + (w16 + gid) * LDP + kb;
            const __nv_bfloat16* a0l = sAl + (w16 + gid) * LDP + kb;
            const __nv_bfloat16* a1h = sAh + (128 + w16 + gid) * LDP + kb;
            const __nv_bfloat16* a1l = sAl + (128 + w16 + gid) * LDP + kb;
            uint32_t ah0[4], al0[4], ah1[4], al1[4];
            ah0[0] = lds32(a0h);               al0[0] = lds32(a0l);
            ah0[1] = lds32(a0h + 8 * LDP);     al0[1] = lds32(a0l + 8 * LDP);
            ah0[2] = lds32(a0h + 8);           al0[2] = lds32(a0l + 8);
            ah0[3] = lds32(a0h + 8 * LDP + 8); al0[3] = lds32(a0l + 8 * LDP + 8);
            ah1[0] = lds32(a1h);               al1[0] = lds32(a1l);
            ah1[1] = lds32(a1h + 8 * LDP);     al1[1] = lds32(a1l + 8 * LDP);
            ah1[2] = lds32(a1h + 8);           al1[2] = lds32(a1l + 8);
            ah1[3] = lds32(a1h + 8 * LDP + 8); al1[3] = lds32(a1l + 8 * LDP + 8);
            #pragma unroll
            for (int j = 0; j < 8; j++) {
                const __nv_bfloat16* br_h = sBh + (j * 8 + gid) * LDP + kb;
                const __nv_bfloat16* br_l = sBl + (j * 8 + gid) * LDP + kb;
                uint32_t bhf[2] = { lds32(br_h), lds32(br_h + 8) };
                uint32_t blf[2] = { lds32(br_l), lds32(br_l + 8) };
                mma16816(acc0[j], ah0, bhf);
                mma16816(acc0[j], ah0, blf);
                mma16816(acc0[j], al0, bhf);
                mma16816(acc1[j], ah1, bhf);
                mma16816(acc1[j], ah1, blf);
                mma16816(acc1[j], al1, bhf);
            }
        }
    }

    int r0 = mb + w16 + gid;
    #pragma unroll
    for (int j = 0; j < 8; j++) {
        int c = nb + j * 8 + 2 * tig;
        float b0 = bias[c], b1 = bias[c + 1];
        *reinterpret_cast<float2*>(out + (size_t)r0 * E + c) =
            make_float2(acc0[j][0] + b0, acc0[j][1] + b1);
        *reinterpret_cast<float2*>(out + (size_t)(r0 + 8) * E + c) =
            make_float2(acc0[j][2] + b0, acc0[j][3] + b1);
        *reinterpret_cast<float2*>(out + (size_t)(r0 + 128) * E + c) =
            make_float2(acc1[j][0] + b0, acc1[j][1] + b1);
        *reinterpret_cast<float2*>(out + (size_t)(r0 + 136) * E + c) =
            make_float2(acc1[j][2] + b0, acc1[j][3] + b1);
    }
}

// ---------------------------------------------------------------------------
extern "C" void kernel_launch(void* const* d_in, const int* in_sizes, int n_in,
                              void* d_out, int out_size)
{
    const float* q    = (const float*)d_in[0];
    const float* k    = (const float*)d_in[1];
    const float* v    = (const float*)d_in[2];
    const float* qw   = (const float*)d_in[3];
    const float* kw   = (const float*)d_in[4];
    const float* W    = (const float*)d_in[5];
    const float* bias = (const float*)d_in[6];
    float* out = (float*)d_out;

    cudaFuncSetAttribute(attn_kernel,
                         cudaFuncAttributeMaxDynamicSharedMemorySize, SMEM_ATTN);
    cudaFuncSetAttribute(proj_kernel,
                         cudaFuncAttributeMaxDynamicSharedMemorySize, SMEM_PROJ);

    prep_kernel<<<(B * S * H) / 8, 256>>>(q, k, v, qw, kw);
    wconv_kernel<<<(E * E) / 256, 256>>>(W);
    attn_kernel<<<dim3(S / BMA, B * H), 256, SMEM_ATTN>>>();
    proj_kernel<<<dim3(E / 64, (B * S) / 256), 256, SMEM_PROJ>>>(bias, out);
}